// round 14
// baseline (speedup 1.0000x reference)
#include <cuda_runtime.h>
#include <math.h>
#include <cstdint>

// Problem constants
#define BB    8
#define CC    128
#define HIN   62
#define HH    64
#define WW    64
#define GG    4
#define GCC   32
#define PP    9
#define NPOS  (BB*HH*WW)   // 32768

// Scratch (device globals; no allocation allowed)
__device__ float g_xt[NPOS*CC];      // tf32-rounded
__device__ float g_y[NPOS*CC];       // tf32-rounded
__device__ float g_xproj[NPOS*CC];   // full fp32 (sampler input)
__device__ float g_dg[NPOS*CC];      // tf32-rounded
__device__ float g_samp[NPOS*CC];    // tf32-rounded
__device__ float g_om[NPOS*CC];      // full fp32 (sampler input)
__device__ float g_w0R[CC*CC];       // conv_w rounded [n][k]
__device__ float g_w1T[CC*CC];       // in_proj_w transposed+rounded [n][k]
__device__ float g_w2P[CC*CC];       // off/mask fused, padded, rounded
__device__ float g_w3T[CC*CC];       // out_proj_w transposed+rounded
__device__ float g_b2[CC];

// ===========================================================================
__device__ __forceinline__ uint32_t f2tf32(float f) {
    uint32_t r;
    asm("cvt.rna.tf32.f32 %0, %1;" : "=r"(r) : "f"(f));
    return r;
}
__device__ __forceinline__ float tf32r(float f) { return __uint_as_float(f2tf32(f)); }
__device__ __forceinline__ void mma_tf32(float* c, const uint32_t* a, const uint32_t* b) {
    asm volatile(
        "mma.sync.aligned.m16n8k8.row.col.f32.tf32.tf32.f32 "
        "{%0,%1,%2,%3}, {%4,%5,%6,%7}, {%8,%9}, {%0,%1,%2,%3};"
        : "+f"(c[0]), "+f"(c[1]), "+f"(c[2]), "+f"(c[3])
        : "r"(a[0]), "r"(a[1]), "r"(a[2]), "r"(a[3]), "r"(b[0]), "r"(b[1]));
}
__device__ __forceinline__ uint32_t smem_u32(const void* p) {
    uint32_t a;
    asm("{ .reg .u64 t; cvta.to.shared.u64 t, %1; cvt.u32.u64 %0, t; }" : "=r"(a) : "l"(p));
    return a;
}
#define CP_ASYNC16(dst, src) \
    asm volatile("cp.async.cg.shared.global [%0], [%1], 16;" \
        :: "r"(dst), "l"(__cvta_generic_to_global(src)) : "memory")
#define CP_COMMIT() asm volatile("cp.async.commit_group;" ::: "memory")
#define CP_WAIT(n)  asm volatile("cp.async.wait_group %0;" :: "n"(n) : "memory")

// ===========================================================================
// Weight prep: transposes + fused/padded off-mask weight; ALL tf32-rounded.
// ===========================================================================
__global__ void prep_weights_kernel(const float* __restrict__ w0, const float* __restrict__ w1,
                                    const float* __restrict__ w3,
                                    const float* __restrict__ offw, const float* __restrict__ maskw,
                                    const float* __restrict__ offb, const float* __restrict__ maskb,
                                    float* __restrict__ w0R, float* __restrict__ w1T,
                                    float* __restrict__ w3T,
                                    float* __restrict__ w2P, float* __restrict__ b2) {
    const int n = blockIdx.x, k = threadIdx.x;
    w0R[n * CC + k] = tf32r(w0[n * CC + k]);     // conv_w already [co][ci]
    w1T[n * CC + k] = tf32r(w1[k * CC + n]);
    w3T[n * CC + k] = tf32r(w3[k * CC + n]);
    float v = 0.f;
    if (n < 72)       v = offw[k * 72 + n];
    else if (n < 108) v = maskw[k * 36 + (n - 72)];
    w2P[n * CC + k] = tf32r(v);
    if (k == 0) b2[n] = (n < 72) ? offb[n] : ((n < 108) ? maskb[n - 72] : 0.f);
}

// ===========================================================================
// x NCHW -> NHWC with 1-px zero border; tf32-rounded (GEMM-A source).
// ===========================================================================
__global__ void pack_x_kernel(const float* __restrict__ x, float* __restrict__ xt) {
    __shared__ float t[32][33];
    const int b  = blockIdx.z >> 6;
    const int h  = blockIdx.z & 63;
    const int w0 = blockIdx.x * 32;
    const int c0 = blockIdx.y * 32;
    const int tx = threadIdx.x, ty = threadIdx.y;
    const int hh = h - 1;
    const int ww = w0 + tx - 1;
    const int cc = c0 + ty;
    float v = 0.f;
    if (hh >= 0 && hh < HIN && ww >= 0 && ww < HIN)
        v = x[(((size_t)b * CC + cc) * HIN + hh) * HIN + ww];
    t[ty][tx] = v;
    __syncthreads();
    xt[(((size_t)b * HH + h) * WW + (w0 + ty)) * CC + (c0 + tx)] = tf32r(t[tx][ty]);
}

// ===========================================================================
// HMMA tf32 GEMM, split-N, 4x K-chunk-32 through a 2-stage cp.async ring.
// CTA = 256 threads (4m x 2n warps); tile = 128 rows x 64 cols.
// smem: 2 stages x (128A + 64B rows) x 36 floats = 55296 B.
// __launch_bounds__(256,3) caps regs at 85 -> 3 CTAs/SM.
// All operands pre-rounded to tf32 -> inner loop is pure LDS + MMA.
// ===========================================================================
#define CH      32
#define CPITCH  36
#define STAGE_F (192 * CPITCH)            // 6912 floats per stage
#define GEMM_SMEM (2 * STAGE_F * 4)       // 55296 bytes
#define SPITCH  132

template <bool TO_NCHW, bool ROUND_OUT>
__global__ void __launch_bounds__(256, 3)
hmma_gemm_kernel(const float* __restrict__ A, const float* __restrict__ Bm,
                 const float* __restrict__ bias, float* __restrict__ Cout) {
    extern __shared__ float smem[];
    const uint32_t sbase = smem_u32(smem);

    const int tid  = threadIdx.x;
    const int lane = tid & 31;
    const int wid  = tid >> 5;
    const int gid  = lane >> 2;
    const int tg   = lane & 3;
    const int warp_m = wid & 3;
    const int warp_n = wid >> 2;
    const int m0 = blockIdx.x * 128;
    const int n0 = blockIdx.y * 64;

    // chunk issue: A 128 rows x 8 float4 (1024), B 64 rows x 8 float4 (512)
    const int irow = tid >> 3;           // 0..31
    const int ic   = (tid & 7) * 4;      // float offset in chunk row
    auto issue = [&](int s, int kc) {
        const uint32_t st = sbase + (uint32_t)(s * STAGE_F * 4);
        #pragma unroll
        for (int i = 0; i < 4; i++) {
            const int row = irow + i * 32;
            CP_ASYNC16(st + (uint32_t)((row * CPITCH + ic) * 4),
                       A + (size_t)(m0 + row) * CC + kc + ic);
        }
        #pragma unroll
        for (int i = 0; i < 2; i++) {
            const int row = irow + i * 32;
            CP_ASYNC16(st + (uint32_t)(((128 + row) * CPITCH + ic) * 4),
                       Bm + (size_t)(n0 + row) * CC + kc + ic);
        }
        CP_COMMIT();
    };

    issue(0, 0);
    issue(1, CH);

    float acc[2][4][4];
    #pragma unroll
    for (int mi = 0; mi < 2; mi++)
        #pragma unroll
        for (int ni = 0; ni < 4; ni++)
            #pragma unroll
            for (int j = 0; j < 4; j++) acc[mi][ni][j] = 0.f;

    const int arow0 = warp_m * 32 + gid;
    const int bcol0 = warp_n * 32 + gid;

    auto mma_chunk = [&](int s) {
        const uint32_t* uA = reinterpret_cast<const uint32_t*>(smem + s * STAGE_F);
        const uint32_t* uB = uA + 128 * CPITCH;
        #pragma unroll
        for (int ks = 0; ks < 4; ks++) {
            const int k8 = ks * 8;
            uint32_t af[2][4];
            #pragma unroll
            for (int mi = 0; mi < 2; mi++) {
                const int r = arow0 + mi * 16;
                af[mi][0] = uA[(r    ) * CPITCH + k8 + tg];
                af[mi][1] = uA[(r + 8) * CPITCH + k8 + tg];
                af[mi][2] = uA[(r    ) * CPITCH + k8 + tg + 4];
                af[mi][3] = uA[(r + 8) * CPITCH + k8 + tg + 4];
            }
            #pragma unroll
            for (int ni = 0; ni < 4; ni++) {
                const int n = bcol0 + ni * 8;
                uint32_t bf[2];
                bf[0] = uB[n * CPITCH + k8 + tg];
                bf[1] = uB[n * CPITCH + k8 + tg + 4];
                mma_tf32(acc[0][ni], af[0], bf);
                mma_tf32(acc[1][ni], af[1], bf);
            }
        }
    };

    // 4 chunks through the 2-stage ring
    CP_WAIT(1);              // chunk0 landed
    __syncthreads();
    mma_chunk(0);
    __syncthreads();
    issue(0, 2 * CH);        // reuse stage 0 for chunk2
    CP_WAIT(1);              // chunk1 landed
    __syncthreads();
    mma_chunk(1);
    __syncthreads();
    issue(1, 3 * CH);        // reuse stage 1 for chunk3
    CP_WAIT(1);              // chunk2 landed
    __syncthreads();
    mma_chunk(0);
    CP_WAIT(0);              // chunk3 landed
    __syncthreads();
    mma_chunk(1);

    float2 bb[4];
    #pragma unroll
    for (int ni = 0; ni < 4; ni++) {
        const int col = n0 + warp_n * 32 + ni * 8 + 2 * tg;
        bb[ni].x = __ldg(bias + col);
        bb[ni].y = __ldg(bias + col + 1);
    }

    auto post = [&](float v) { return ROUND_OUT ? tf32r(v) : v; };

    if (!TO_NCHW) {
        #pragma unroll
        for (int mi = 0; mi < 2; mi++) {
            const int r0 = m0 + arow0 + mi * 16;
            #pragma unroll
            for (int ni = 0; ni < 4; ni++) {
                const int col = n0 + warp_n * 32 + ni * 8 + 2 * tg;
                float2 v0 = make_float2(post(acc[mi][ni][0] + bb[ni].x), post(acc[mi][ni][1] + bb[ni].y));
                float2 v1 = make_float2(post(acc[mi][ni][2] + bb[ni].x), post(acc[mi][ni][3] + bb[ni].y));
                *reinterpret_cast<float2*>(Cout + (size_t)r0 * CC + col)       = v0;
                *reinterpret_cast<float2*>(Cout + (size_t)(r0 + 8) * CC + col) = v1;
            }
        }
    } else {
        // Stage transposed [64 cols][128 rows] pitch 132 across BOTH stage bufs
        // (64*132*4 = 33792 B <= 55296 B smem).
        __syncthreads();
        float* sCT = smem;
        #pragma unroll
        for (int mi = 0; mi < 2; mi++) {
            #pragma unroll
            for (int ni = 0; ni < 4; ni++) {
                const int col = warp_n * 32 + ni * 8 + 2 * tg;
                const int r   = arow0 + mi * 16;
                sCT[(col    ) * SPITCH + r    ] = acc[mi][ni][0] + bb[ni].x;
                sCT[(col + 1) * SPITCH + r    ] = acc[mi][ni][1] + bb[ni].y;
                sCT[(col    ) * SPITCH + r + 8] = acc[mi][ni][2] + bb[ni].x;
                sCT[(col + 1) * SPITCH + r + 8] = acc[mi][ni][3] + bb[ni].y;
            }
        }
        __syncthreads();
        const int b       = m0 >> 12;
        const int inbatch = m0 & 4095;
        #pragma unroll
        for (int i = 0; i < 8; i++) {
            const int idx = i * 256 + tid;
            const int col = idx >> 5;
            const int rc  = idx & 31;
            const float4 v = *reinterpret_cast<const float4*>(sCT + col * SPITCH + rc * 4);
            *reinterpret_cast<float4*>(
                Cout + ((size_t)b * CC + (n0 + col)) * (HH * WW) + inbatch + rc * 4) = v;
        }
    }
}

// ===========================================================================
// Depthwise 3x3 (pad 1) + bias + LayerNorm(C) + exact GELU; tf32-rounded out.
// ===========================================================================
__global__ void __launch_bounds__(256)
dw_ln_gelu_kernel(const float* __restrict__ y,
                  const float* __restrict__ dww,
                  const float* __restrict__ dwb,
                  const float* __restrict__ lng,
                  const float* __restrict__ lnb,
                  float* __restrict__ out) {
    __shared__ float sW[9 * CC];
    const int tid = threadIdx.x;
    for (int i = tid; i < 9 * CC; i += 256) {
        const int c = i / 9, tap = i % 9;
        sW[tap * CC + c] = dww[i];
    }
    __syncthreads();

    const int wid  = tid >> 5;
    const int lane = tid & 31;
    const int pos  = blockIdx.x * 8 + wid;
    const int b = pos >> 12;
    const int h = (pos >> 6) & 63;
    const int w = pos & 63;
    const int c4 = lane * 4;

    const float4 bv = __ldg(reinterpret_cast<const float4*>(dwb + c4));
    float4 acc = bv;
    const float* ybase = y + (((size_t)b * HH + h) * WW + w) * CC + c4;
    #pragma unroll
    for (int i = 0; i < 3; i++) {
        const int hh = h + i - 1;
        if ((unsigned)hh >= (unsigned)HH) continue;
        #pragma unroll
        for (int j = 0; j < 3; j++) {
            const int ww = w + j - 1;
            if ((unsigned)ww >= (unsigned)WW) continue;
            const float4 v = __ldg(reinterpret_cast<const float4*>(
                ybase + ((i - 1) * WW + (j - 1)) * CC));
            const float4 wt = *reinterpret_cast<const float4*>(sW + (i * 3 + j) * CC + c4);
            acc.x = fmaf(v.x, wt.x, acc.x);
            acc.y = fmaf(v.y, wt.y, acc.y);
            acc.z = fmaf(v.z, wt.z, acc.z);
            acc.w = fmaf(v.w, wt.w, acc.w);
        }
    }

    float s  = acc.x + acc.y + acc.z + acc.w;
    float s2 = acc.x * acc.x + acc.y * acc.y + acc.z * acc.z + acc.w * acc.w;
    #pragma unroll
    for (int o = 16; o > 0; o >>= 1) {
        s  += __shfl_xor_sync(0xFFFFFFFFu, s,  o);
        s2 += __shfl_xor_sync(0xFFFFFFFFu, s2, o);
    }
    const float mean = s * (1.f / CC);
    const float var  = s2 * (1.f / CC) - mean * mean;
    const float rstd = rsqrtf(var + 1e-5f);

    const float4 gv = __ldg(reinterpret_cast<const float4*>(lng + c4));
    const float4 betav = __ldg(reinterpret_cast<const float4*>(lnb + c4));
    float4 o4;
    {
        float v0 = (acc.x - mean) * rstd * gv.x + betav.x;
        float v1 = (acc.y - mean) * rstd * gv.y + betav.y;
        float v2 = (acc.z - mean) * rstd * gv.z + betav.z;
        float v3 = (acc.w - mean) * rstd * gv.w + betav.w;
        const float k = 0.70710678118654752440f;
        o4.x = tf32r(0.5f * v0 * (1.f + erff(v0 * k)));
        o4.y = tf32r(0.5f * v1 * (1.f + erff(v1 * k)));
        o4.z = tf32r(0.5f * v2 * (1.f + erff(v2 * k)));
        o4.w = tf32r(0.5f * v3 * (1.f + erff(v3 * k)));
    }
    *reinterpret_cast<float4*>(out + (size_t)pos * CC + c4) = o4;
}

// ===========================================================================
// DCNv3 bilinear sampler + fused group softmax; tf32-rounded out (GEMM-A).
// ===========================================================================
__global__ void __launch_bounds__(256)
sampler_kernel(const float* __restrict__ xproj,
               const float* __restrict__ om,
               float* __restrict__ out) {
    __shared__ float sOM[8][112];
    const int tid  = threadIdx.x;
    const int wid  = tid >> 5;
    const int lane = tid & 31;
    const int pos  = blockIdx.x * 8 + wid;
    const int b = pos >> 12;
    const int h = (pos >> 6) & 63;
    const int w = pos & 63;
    const int g  = lane >> 3;
    const int c4 = (lane & 7) * 4;

    #pragma unroll
    for (int r = 0; r < 4; r++) {
        const int i = r * 32 + lane;
        if (i < 108) sOM[wid][i] = __ldg(om + (size_t)pos * CC + i);
    }
    __syncwarp();

    const float* logit = &sOM[wid][72 + g * 9];
    float mx = -1e30f;
    #pragma unroll
    for (int p = 0; p < 9; p++) mx = fmaxf(mx, logit[p]);
    float se = 0.f;
    float ex[9];
    #pragma unroll
    for (int p = 0; p < 9; p++) { ex[p] = expf(logit[p] - mx); se += ex[p]; }
    const float inv_se = 1.f / se;

    const float* base = xproj + (size_t)b * (HH * WW * CC) + g * GCC + c4;
    float4 acc = make_float4(0.f, 0.f, 0.f, 0.f);
    #pragma unroll
    for (int p = 0; p < PP; p++) {
        const int gp = g * 9 + p;
        const float fix = (float)(w + p / 3) + sOM[wid][2 * gp];
        const float fiy = (float)(h + p % 3) + sOM[wid][2 * gp + 1];
        const float x0f = floorf(fix), y0f = floorf(fiy);
        const float fx = fix - x0f, fy = fiy - y0f;
        const int x0 = (int)x0f, y0 = (int)y0f;
        const float m = ex[p] * inv_se;

        const bool xv0 = (x0 >= 1) && (x0 <= 64);
        const bool xv1 = (x0 >= 0) && (x0 <= 63);
        const bool yv0 = (y0 >= 1) && (y0 <= 64);
        const bool yv1 = (y0 >= 0) && (y0 <= 63);
        float4 v00 = make_float4(0,0,0,0), v10 = v00, v01 = v00, v11 = v00;
        if (yv0 && xv0) v00 = __ldg(reinterpret_cast<const float4*>(base + ((size_t)(y0 - 1) * WW + (x0 - 1)) * CC));
        if (yv0 && xv1) v10 = __ldg(reinterpret_cast<const float4*>(base + ((size_t)(y0 - 1) * WW + (x0    )) * CC));
        if (yv1 && xv0) v01 = __ldg(reinterpret_cast<const float4*>(base + ((size_t)(y0    ) * WW + (x0 - 1)) * CC));
        if (yv1 && xv1) v11 = __ldg(reinterpret_cast<const float4*>(base + ((size_t)(y0    ) * WW + (x0    )) * CC));

        const float w00 = (1.f - fx) * (1.f - fy) * m;
        const float w10 = fx * (1.f - fy) * m;
        const float w01 = (1.f - fx) * fy * m;
        const float w11 = fx * fy * m;
        acc.x += v00.x * w00 + v10.x * w10 + v01.x * w01 + v11.x * w11;
        acc.y += v00.y * w00 + v10.y * w10 + v01.y * w01 + v11.y * w11;
        acc.z += v00.z * w00 + v10.z * w10 + v01.z * w01 + v11.z * w11;
        acc.w += v00.w * w00 + v10.w * w10 + v01.w * w01 + v11.w * w11;
    }
    float4 o4;
    o4.x = tf32r(acc.x); o4.y = tf32r(acc.y); o4.z = tf32r(acc.z); o4.w = tf32r(acc.w);
    *reinterpret_cast<float4*>(out + (size_t)pos * CC + g * GCC + c4) = o4;
}

// ===========================================================================
extern "C" void kernel_launch(void* const* d_in, const int* in_sizes, int n_in,
                              void* d_out, int out_size) {
    const float* x         = (const float*)d_in[0];
    const float* conv_w    = (const float*)d_in[1];
    const float* conv_b    = (const float*)d_in[2];
    const float* in_proj_w = (const float*)d_in[3];
    const float* in_proj_b = (const float*)d_in[4];
    const float* dw_w      = (const float*)d_in[5];
    const float* dw_b      = (const float*)d_in[6];
    const float* ln_g      = (const float*)d_in[7];
    const float* ln_b      = (const float*)d_in[8];
    const float* off_w     = (const float*)d_in[9];
    const float* off_b     = (const float*)d_in[10];
    const float* mask_w    = (const float*)d_in[11];
    const float* mask_b    = (const float*)d_in[12];
    const float* out_w     = (const float*)d_in[13];
    const float* out_b     = (const float*)d_in[14];
    float* out = (float*)d_out;

    float *xt, *y, *xproj, *dg, *samp, *omp, *w0R, *w1T, *w2P, *w3T, *b2;
    cudaGetSymbolAddress((void**)&xt,    g_xt);
    cudaGetSymbolAddress((void**)&y,     g_y);
    cudaGetSymbolAddress((void**)&xproj, g_xproj);
    cudaGetSymbolAddress((void**)&dg,    g_dg);
    cudaGetSymbolAddress((void**)&samp,  g_samp);
    cudaGetSymbolAddress((void**)&omp,   g_om);
    cudaGetSymbolAddress((void**)&w0R,   g_w0R);
    cudaGetSymbolAddress((void**)&w1T,   g_w1T);
    cudaGetSymbolAddress((void**)&w2P,   g_w2P);
    cudaGetSymbolAddress((void**)&w3T,   g_w3T);
    cudaGetSymbolAddress((void**)&b2,    g_b2);

    static cudaStream_t s1 = nullptr;
    static cudaEvent_t eFork = nullptr, ePrep = nullptr, eConv = nullptr, eProj = nullptr;
    static bool init_done = false;
    if (!init_done) {
        cudaFuncSetAttribute((const void*)hmma_gemm_kernel<false, true>,
                             cudaFuncAttributeMaxDynamicSharedMemorySize, GEMM_SMEM);
        cudaFuncSetAttribute((const void*)hmma_gemm_kernel<false, false>,
                             cudaFuncAttributeMaxDynamicSharedMemorySize, GEMM_SMEM);
        cudaFuncSetAttribute((const void*)hmma_gemm_kernel<true, false>,
                             cudaFuncAttributeMaxDynamicSharedMemorySize, GEMM_SMEM);
        cudaStreamCreateWithFlags(&s1, cudaStreamNonBlocking);
        cudaEventCreateWithFlags(&eFork, cudaEventDisableTiming);
        cudaEventCreateWithFlags(&ePrep, cudaEventDisableTiming);
        cudaEventCreateWithFlags(&eConv, cudaEventDisableTiming);
        cudaEventCreateWithFlags(&eProj, cudaEventDisableTiming);
        init_done = true;
    }

    const dim3 tblk(32, 32);
    const dim3 tgrid(2, 4, BB * HH);
    const dim3 ggrid(NPOS / 128, 2);

    // ---- fork side stream ----
    cudaEventRecord(eFork, 0);
    cudaStreamWaitEvent(s1, eFork, 0);

    // s1: weight prep (rounded weights)
    prep_weights_kernel<<<CC, CC, 0, s1>>>(conv_w, in_proj_w, out_w, off_w, mask_w,
                                           off_b, mask_b, w0R, w1T, w3T, w2P, b2);
    cudaEventRecord(ePrep, s1);

    // s0: pack (rounds xt); conv waits for prep (overlapped with pack)
    pack_x_kernel<<<tgrid, tblk>>>(x, xt);
    cudaStreamWaitEvent(0, ePrep, 0);
    hmma_gemm_kernel<false, true><<<ggrid, 256, GEMM_SMEM>>>(xt, w0R, conv_b, y);
    cudaEventRecord(eConv, 0);

    // s1: in_proj (full fp32 out; parallel with dw branch)
    cudaStreamWaitEvent(s1, eConv, 0);
    hmma_gemm_kernel<false, false><<<ggrid, 256, GEMM_SMEM, s1>>>(y, w1T, in_proj_b, xproj);
    cudaEventRecord(eProj, s1);

    // s0: dw+LN+GELU (rounds dg) -> off_mask GEMM (full fp32 out)
    dw_ln_gelu_kernel<<<NPOS / 8, 256>>>(y, dw_w, dw_b, ln_g, ln_b, dg);
    hmma_gemm_kernel<false, false><<<ggrid, 256, GEMM_SMEM>>>(dg, w2P, b2, omp);

    // join: sampler needs xproj (s1) + omp (s0); rounds samp
    cudaStreamWaitEvent(0, eProj, 0);
    sampler_kernel<<<NPOS / 8, 256>>>(xproj, omp, samp);

    // out_proj writes NCHW directly (full fp32)
    hmma_gemm_kernel<true, false><<<ggrid, 256, GEMM_SMEM>>>(samp, w3T, out_b, out);
}

// round 15
// speedup vs baseline: 1.0393x; 1.0393x over previous
#include <cuda_runtime.h>
#include <math.h>
#include <cstdint>

// Problem constants
#define BB    8
#define CC    128
#define HIN   62
#define HH    64
#define WW    64
#define GG    4
#define GCC   32
#define PP    9
#define NPOS  (BB*HH*WW)   // 32768

// Scratch (device globals; no allocation allowed)
__device__ float g_xt[NPOS*CC];      // tf32-rounded
__device__ float g_y[NPOS*CC];       // tf32-rounded
__device__ float g_xproj[NPOS*CC];   // full fp32 (sampler input)
__device__ float g_dg[NPOS*CC];      // tf32-rounded
__device__ float g_samp[NPOS*CC];    // tf32-rounded
__device__ float g_om[NPOS*CC];      // full fp32 (sampler input)
__device__ float g_w0R[CC*CC];       // conv_w rounded [n][k]
__device__ float g_w1T[CC*CC];       // in_proj_w transposed+rounded [n][k]
__device__ float g_w2P[CC*CC];       // off/mask fused, padded, rounded
__device__ float g_w3T[CC*CC];       // out_proj_w transposed+rounded
__device__ float g_b2[CC];

// ===========================================================================
__device__ __forceinline__ uint32_t f2tf32(float f) {
    uint32_t r;
    asm("cvt.rna.tf32.f32 %0, %1;" : "=r"(r) : "f"(f));
    return r;
}
__device__ __forceinline__ float tf32r(float f) { return __uint_as_float(f2tf32(f)); }
__device__ __forceinline__ void mma_tf32(float* c, const uint32_t* a, const uint32_t* b) {
    asm volatile(
        "mma.sync.aligned.m16n8k8.row.col.f32.tf32.tf32.f32 "
        "{%0,%1,%2,%3}, {%4,%5,%6,%7}, {%8,%9}, {%0,%1,%2,%3};"
        : "+f"(c[0]), "+f"(c[1]), "+f"(c[2]), "+f"(c[3])
        : "r"(a[0]), "r"(a[1]), "r"(a[2]), "r"(a[3]), "r"(b[0]), "r"(b[1]));
}
__device__ __forceinline__ uint32_t smem_u32(const void* p) {
    uint32_t a;
    asm("{ .reg .u64 t; cvta.to.shared.u64 t, %1; cvt.u32.u64 %0, t; }" : "=r"(a) : "l"(p));
    return a;
}
#define CP_ASYNC16(dst, src) \
    asm volatile("cp.async.cg.shared.global [%0], [%1], 16;" \
        :: "r"(dst), "l"(__cvta_generic_to_global(src)) : "memory")
#define CP_COMMIT() asm volatile("cp.async.commit_group;" ::: "memory")
#define CP_WAIT(n)  asm volatile("cp.async.wait_group %0;" :: "n"(n) : "memory")

// ===========================================================================
// Weight prep: transposes + fused/padded off-mask weight; ALL tf32-rounded.
// ===========================================================================
__global__ void prep_weights_kernel(const float* __restrict__ w0, const float* __restrict__ w1,
                                    const float* __restrict__ w3,
                                    const float* __restrict__ offw, const float* __restrict__ maskw,
                                    const float* __restrict__ offb, const float* __restrict__ maskb,
                                    float* __restrict__ w0R, float* __restrict__ w1T,
                                    float* __restrict__ w3T,
                                    float* __restrict__ w2P, float* __restrict__ b2) {
    const int n = blockIdx.x, k = threadIdx.x;
    w0R[n * CC + k] = tf32r(w0[n * CC + k]);     // conv_w already [co][ci]
    w1T[n * CC + k] = tf32r(w1[k * CC + n]);
    w3T[n * CC + k] = tf32r(w3[k * CC + n]);
    float v = 0.f;
    if (n < 72)       v = offw[k * 72 + n];
    else if (n < 108) v = maskw[k * 36 + (n - 72)];
    w2P[n * CC + k] = tf32r(v);
    if (k == 0) b2[n] = (n < 72) ? offb[n] : ((n < 108) ? maskb[n - 72] : 0.f);
}

// ===========================================================================
// x NCHW -> NHWC with 1-px zero border; tf32-rounded (GEMM-A source).
// ===========================================================================
__global__ void pack_x_kernel(const float* __restrict__ x, float* __restrict__ xt) {
    __shared__ float t[32][33];
    const int b  = blockIdx.z >> 6;
    const int h  = blockIdx.z & 63;
    const int w0 = blockIdx.x * 32;
    const int c0 = blockIdx.y * 32;
    const int tx = threadIdx.x, ty = threadIdx.y;
    const int hh = h - 1;
    const int ww = w0 + tx - 1;
    const int cc = c0 + ty;
    float v = 0.f;
    if (hh >= 0 && hh < HIN && ww >= 0 && ww < HIN)
        v = x[(((size_t)b * CC + cc) * HIN + hh) * HIN + ww];
    t[ty][tx] = v;
    __syncthreads();
    xt[(((size_t)b * HH + h) * WW + (w0 + ty)) * CC + (c0 + tx)] = tf32r(t[tx][ty]);
}

// ===========================================================================
// HMMA tf32 GEMM, FULL-N tile: M128 x N128, 4x K-chunk-32, 2-stage ring.
// CTA = 256 threads = 8 warps (4m x 2n); warp tile = 32 rows x 64 cols.
// smem: 2 stages x (128A + 128B rows) x 36 floats = 73728 B -> 2 CTAs/SM.
// Grid = 256 CTAs -> SINGLE WAVE at 2 CTAs/SM. A read once.
// All operands pre-rounded to tf32 -> inner loop is pure LDS + MMA.
// ===========================================================================
#define CH      32
#define CPITCH  36
#define STAGE_F (256 * CPITCH)            // 9216 floats per stage
#define GEMM_SMEM (2 * STAGE_F * 4)       // 73728 bytes
#define SPITCH  132

template <bool TO_NCHW, bool ROUND_OUT>
__global__ void __launch_bounds__(256, 2)
hmma_gemm_kernel(const float* __restrict__ A, const float* __restrict__ Bm,
                 const float* __restrict__ bias, float* __restrict__ Cout) {
    extern __shared__ float smem[];
    const uint32_t sbase = smem_u32(smem);

    const int tid  = threadIdx.x;
    const int lane = tid & 31;
    const int wid  = tid >> 5;
    const int gid  = lane >> 2;
    const int tg   = lane & 3;
    const int warp_m = wid & 3;   // 32-row subtiles
    const int warp_n = wid >> 2;  // 64-col subtiles
    const int m0 = blockIdx.x * 128;

    // chunk issue: A 128 rows + B 128 rows, 8 float4 each = 2048 f4; 8/thread
    const int irow = tid >> 3;           // 0..31
    const int ic   = (tid & 7) * 4;      // float offset in chunk row
    auto issue = [&](int s, int kc) {
        const uint32_t st = sbase + (uint32_t)(s * STAGE_F * 4);
        #pragma unroll
        for (int i = 0; i < 4; i++) {
            const int row = irow + i * 32;
            CP_ASYNC16(st + (uint32_t)((row * CPITCH + ic) * 4),
                       A + (size_t)(m0 + row) * CC + kc + ic);
        }
        #pragma unroll
        for (int i = 0; i < 4; i++) {
            const int row = irow + i * 32;
            CP_ASYNC16(st + (uint32_t)(((128 + row) * CPITCH + ic) * 4),
                       Bm + (size_t)row * CC + kc + ic);
        }
        CP_COMMIT();
    };

    issue(0, 0);
    issue(1, CH);

    float acc[2][8][4];
    #pragma unroll
    for (int mi = 0; mi < 2; mi++)
        #pragma unroll
        for (int ni = 0; ni < 8; ni++)
            #pragma unroll
            for (int j = 0; j < 4; j++) acc[mi][ni][j] = 0.f;

    const int arow0 = warp_m * 32 + gid;
    const int bcol0 = warp_n * 64 + gid;

    auto mma_chunk = [&](int s) {
        const uint32_t* uA = reinterpret_cast<const uint32_t*>(smem + s * STAGE_F);
        const uint32_t* uB = uA + 128 * CPITCH;
        #pragma unroll
        for (int ks = 0; ks < 4; ks++) {
            const int k8 = ks * 8;
            uint32_t af[2][4];
            #pragma unroll
            for (int mi = 0; mi < 2; mi++) {
                const int r = arow0 + mi * 16;
                af[mi][0] = uA[(r    ) * CPITCH + k8 + tg];
                af[mi][1] = uA[(r + 8) * CPITCH + k8 + tg];
                af[mi][2] = uA[(r    ) * CPITCH + k8 + tg + 4];
                af[mi][3] = uA[(r + 8) * CPITCH + k8 + tg + 4];
            }
            #pragma unroll
            for (int ni = 0; ni < 8; ni++) {
                const int n = bcol0 + ni * 8;
                uint32_t bf[2];
                bf[0] = uB[n * CPITCH + k8 + tg];
                bf[1] = uB[n * CPITCH + k8 + tg + 4];
                mma_tf32(acc[0][ni], af[0], bf);
                mma_tf32(acc[1][ni], af[1], bf);
            }
        }
    };

    // 4 chunks through the 2-stage ring
    CP_WAIT(1);
    __syncthreads();
    mma_chunk(0);
    __syncthreads();
    issue(0, 2 * CH);
    CP_WAIT(1);
    __syncthreads();
    mma_chunk(1);
    __syncthreads();
    issue(1, 3 * CH);
    CP_WAIT(1);
    __syncthreads();
    mma_chunk(0);
    CP_WAIT(0);
    __syncthreads();
    mma_chunk(1);

    float2 bb[8];
    #pragma unroll
    for (int ni = 0; ni < 8; ni++) {
        const int col = warp_n * 64 + ni * 8 + 2 * tg;
        bb[ni].x = __ldg(bias + col);
        bb[ni].y = __ldg(bias + col + 1);
    }

    auto post = [&](float v) { return ROUND_OUT ? tf32r(v) : v; };

    if (!TO_NCHW) {
        #pragma unroll
        for (int mi = 0; mi < 2; mi++) {
            const int r0 = m0 + arow0 + mi * 16;
            #pragma unroll
            for (int ni = 0; ni < 8; ni++) {
                const int col = warp_n * 64 + ni * 8 + 2 * tg;
                float2 v0 = make_float2(post(acc[mi][ni][0] + bb[ni].x), post(acc[mi][ni][1] + bb[ni].y));
                float2 v1 = make_float2(post(acc[mi][ni][2] + bb[ni].x), post(acc[mi][ni][3] + bb[ni].y));
                *reinterpret_cast<float2*>(Cout + (size_t)r0 * CC + col)       = v0;
                *reinterpret_cast<float2*>(Cout + (size_t)(r0 + 8) * CC + col) = v1;
            }
        }
    } else {
        // Stage transposed [128 cols][128 rows] pitch 132 = 67.6KB <= 73.7KB.
        __syncthreads();
        float* sCT = smem;
        #pragma unroll
        for (int mi = 0; mi < 2; mi++) {
            #pragma unroll
            for (int ni = 0; ni < 8; ni++) {
                const int col = warp_n * 64 + ni * 8 + 2 * tg;
                const int r   = arow0 + mi * 16;
                sCT[(col    ) * SPITCH + r    ] = acc[mi][ni][0] + bb[ni].x;
                sCT[(col + 1) * SPITCH + r    ] = acc[mi][ni][1] + bb[ni].y;
                sCT[(col    ) * SPITCH + r + 8] = acc[mi][ni][2] + bb[ni].x;
                sCT[(col + 1) * SPITCH + r + 8] = acc[mi][ni][3] + bb[ni].y;
            }
        }
        __syncthreads();
        const int b       = m0 >> 12;
        const int inbatch = m0 & 4095;
        #pragma unroll
        for (int i = 0; i < 16; i++) {
            const int idx = i * 256 + tid;       // 4096 float4s: 128 cols x 32
            const int col = idx >> 5;
            const int rc  = idx & 31;
            const float4 v = *reinterpret_cast<const float4*>(sCT + col * SPITCH + rc * 4);
            *reinterpret_cast<float4*>(
                Cout + ((size_t)b * CC + col) * (HH * WW) + inbatch + rc * 4) = v;
        }
    }
}

// ===========================================================================
// Depthwise 3x3 (pad 1) + bias + LayerNorm(C) + exact GELU; tf32-rounded out.
// ===========================================================================
__global__ void __launch_bounds__(256)
dw_ln_gelu_kernel(const float* __restrict__ y,
                  const float* __restrict__ dww,
                  const float* __restrict__ dwb,
                  const float* __restrict__ lng,
                  const float* __restrict__ lnb,
                  float* __restrict__ out) {
    __shared__ float sW[9 * CC];
    const int tid = threadIdx.x;
    for (int i = tid; i < 9 * CC; i += 256) {
        const int c = i / 9, tap = i % 9;
        sW[tap * CC + c] = dww[i];
    }
    __syncthreads();

    const int wid  = tid >> 5;
    const int lane = tid & 31;
    const int pos  = blockIdx.x * 8 + wid;
    const int b = pos >> 12;
    const int h = (pos >> 6) & 63;
    const int w = pos & 63;
    const int c4 = lane * 4;

    const float4 bv = __ldg(reinterpret_cast<const float4*>(dwb + c4));
    float4 acc = bv;
    const float* ybase = y + (((size_t)b * HH + h) * WW + w) * CC + c4;
    #pragma unroll
    for (int i = 0; i < 3; i++) {
        const int hh = h + i - 1;
        if ((unsigned)hh >= (unsigned)HH) continue;
        #pragma unroll
        for (int j = 0; j < 3; j++) {
            const int ww = w + j - 1;
            if ((unsigned)ww >= (unsigned)WW) continue;
            const float4 v = __ldg(reinterpret_cast<const float4*>(
                ybase + ((i - 1) * WW + (j - 1)) * CC));
            const float4 wt = *reinterpret_cast<const float4*>(sW + (i * 3 + j) * CC + c4);
            acc.x = fmaf(v.x, wt.x, acc.x);
            acc.y = fmaf(v.y, wt.y, acc.y);
            acc.z = fmaf(v.z, wt.z, acc.z);
            acc.w = fmaf(v.w, wt.w, acc.w);
        }
    }

    float s  = acc.x + acc.y + acc.z + acc.w;
    float s2 = acc.x * acc.x + acc.y * acc.y + acc.z * acc.z + acc.w * acc.w;
    #pragma unroll
    for (int o = 16; o > 0; o >>= 1) {
        s  += __shfl_xor_sync(0xFFFFFFFFu, s,  o);
        s2 += __shfl_xor_sync(0xFFFFFFFFu, s2, o);
    }
    const float mean = s * (1.f / CC);
    const float var  = s2 * (1.f / CC) - mean * mean;
    const float rstd = rsqrtf(var + 1e-5f);

    const float4 gv = __ldg(reinterpret_cast<const float4*>(lng + c4));
    const float4 betav = __ldg(reinterpret_cast<const float4*>(lnb + c4));
    float4 o4;
    {
        float v0 = (acc.x - mean) * rstd * gv.x + betav.x;
        float v1 = (acc.y - mean) * rstd * gv.y + betav.y;
        float v2 = (acc.z - mean) * rstd * gv.z + betav.z;
        float v3 = (acc.w - mean) * rstd * gv.w + betav.w;
        const float k = 0.70710678118654752440f;
        o4.x = tf32r(0.5f * v0 * (1.f + erff(v0 * k)));
        o4.y = tf32r(0.5f * v1 * (1.f + erff(v1 * k)));
        o4.z = tf32r(0.5f * v2 * (1.f + erff(v2 * k)));
        o4.w = tf32r(0.5f * v3 * (1.f + erff(v3 * k)));
    }
    *reinterpret_cast<float4*>(out + (size_t)pos * CC + c4) = o4;
}

// ===========================================================================
// DCNv3 bilinear sampler + fused group softmax; tf32-rounded out (GEMM-A).
// ===========================================================================
__global__ void __launch_bounds__(256)
sampler_kernel(const float* __restrict__ xproj,
               const float* __restrict__ om,
               float* __restrict__ out) {
    __shared__ float sOM[8][112];
    const int tid  = threadIdx.x;
    const int wid  = tid >> 5;
    const int lane = tid & 31;
    const int pos  = blockIdx.x * 8 + wid;
    const int b = pos >> 12;
    const int h = (pos >> 6) & 63;
    const int w = pos & 63;
    const int g  = lane >> 3;
    const int c4 = (lane & 7) * 4;

    #pragma unroll
    for (int r = 0; r < 4; r++) {
        const int i = r * 32 + lane;
        if (i < 108) sOM[wid][i] = __ldg(om + (size_t)pos * CC + i);
    }
    __syncwarp();

    const float* logit = &sOM[wid][72 + g * 9];
    float mx = -1e30f;
    #pragma unroll
    for (int p = 0; p < 9; p++) mx = fmaxf(mx, logit[p]);
    float se = 0.f;
    float ex[9];
    #pragma unroll
    for (int p = 0; p < 9; p++) { ex[p] = expf(logit[p] - mx); se += ex[p]; }
    const float inv_se = 1.f / se;

    const float* base = xproj + (size_t)b * (HH * WW * CC) + g * GCC + c4;
    float4 acc = make_float4(0.f, 0.f, 0.f, 0.f);
    #pragma unroll
    for (int p = 0; p < PP; p++) {
        const int gp = g * 9 + p;
        const float fix = (float)(w + p / 3) + sOM[wid][2 * gp];
        const float fiy = (float)(h + p % 3) + sOM[wid][2 * gp + 1];
        const float x0f = floorf(fix), y0f = floorf(fiy);
        const float fx = fix - x0f, fy = fiy - y0f;
        const int x0 = (int)x0f, y0 = (int)y0f;
        const float m = ex[p] * inv_se;

        const bool xv0 = (x0 >= 1) && (x0 <= 64);
        const bool xv1 = (x0 >= 0) && (x0 <= 63);
        const bool yv0 = (y0 >= 1) && (y0 <= 64);
        const bool yv1 = (y0 >= 0) && (y0 <= 63);
        float4 v00 = make_float4(0,0,0,0), v10 = v00, v01 = v00, v11 = v00;
        if (yv0 && xv0) v00 = __ldg(reinterpret_cast<const float4*>(base + ((size_t)(y0 - 1) * WW + (x0 - 1)) * CC));
        if (yv0 && xv1) v10 = __ldg(reinterpret_cast<const float4*>(base + ((size_t)(y0 - 1) * WW + (x0    )) * CC));
        if (yv1 && xv0) v01 = __ldg(reinterpret_cast<const float4*>(base + ((size_t)(y0    ) * WW + (x0 - 1)) * CC));
        if (yv1 && xv1) v11 = __ldg(reinterpret_cast<const float4*>(base + ((size_t)(y0    ) * WW + (x0    )) * CC));

        const float w00 = (1.f - fx) * (1.f - fy) * m;
        const float w10 = fx * (1.f - fy) * m;
        const float w01 = (1.f - fx) * fy * m;
        const float w11 = fx * fy * m;
        acc.x += v00.x * w00 + v10.x * w10 + v01.x * w01 + v11.x * w11;
        acc.y += v00.y * w00 + v10.y * w10 + v01.y * w01 + v11.y * w11;
        acc.z += v00.z * w00 + v10.z * w10 + v01.z * w01 + v11.z * w11;
        acc.w += v00.w * w00 + v10.w * w10 + v01.w * w01 + v11.w * w11;
    }
    float4 o4;
    o4.x = tf32r(acc.x); o4.y = tf32r(acc.y); o4.z = tf32r(acc.z); o4.w = tf32r(acc.w);
    *reinterpret_cast<float4*>(out + (size_t)pos * CC + g * GCC + c4) = o4;
}

// ===========================================================================
extern "C" void kernel_launch(void* const* d_in, const int* in_sizes, int n_in,
                              void* d_out, int out_size) {
    const float* x         = (const float*)d_in[0];
    const float* conv_w    = (const float*)d_in[1];
    const float* conv_b    = (const float*)d_in[2];
    const float* in_proj_w = (const float*)d_in[3];
    const float* in_proj_b = (const float*)d_in[4];
    const float* dw_w      = (const float*)d_in[5];
    const float* dw_b      = (const float*)d_in[6];
    const float* ln_g      = (const float*)d_in[7];
    const float* ln_b      = (const float*)d_in[8];
    const float* off_w     = (const float*)d_in[9];
    const float* off_b     = (const float*)d_in[10];
    const float* mask_w    = (const float*)d_in[11];
    const float* mask_b    = (const float*)d_in[12];
    const float* out_w     = (const float*)d_in[13];
    const float* out_b     = (const float*)d_in[14];
    float* out = (float*)d_out;

    float *xt, *y, *xproj, *dg, *samp, *omp, *w0R, *w1T, *w2P, *w3T, *b2;
    cudaGetSymbolAddress((void**)&xt,    g_xt);
    cudaGetSymbolAddress((void**)&y,     g_y);
    cudaGetSymbolAddress((void**)&xproj, g_xproj);
    cudaGetSymbolAddress((void**)&dg,    g_dg);
    cudaGetSymbolAddress((void**)&samp,  g_samp);
    cudaGetSymbolAddress((void**)&omp,   g_om);
    cudaGetSymbolAddress((void**)&w0R,   g_w0R);
    cudaGetSymbolAddress((void**)&w1T,   g_w1T);
    cudaGetSymbolAddress((void**)&w2P,   g_w2P);
    cudaGetSymbolAddress((void**)&w3T,   g_w3T);
    cudaGetSymbolAddress((void**)&b2,    g_b2);

    static cudaStream_t s1 = nullptr;
    static cudaEvent_t eFork = nullptr, ePrep = nullptr, eConv = nullptr, eProj = nullptr;
    static bool init_done = false;
    if (!init_done) {
        cudaFuncSetAttribute((const void*)hmma_gemm_kernel<false, true>,
                             cudaFuncAttributeMaxDynamicSharedMemorySize, GEMM_SMEM);
        cudaFuncSetAttribute((const void*)hmma_gemm_kernel<false, false>,
                             cudaFuncAttributeMaxDynamicSharedMemorySize, GEMM_SMEM);
        cudaFuncSetAttribute((const void*)hmma_gemm_kernel<true, false>,
                             cudaFuncAttributeMaxDynamicSharedMemorySize, GEMM_SMEM);
        cudaStreamCreateWithFlags(&s1, cudaStreamNonBlocking);
        cudaEventCreateWithFlags(&eFork, cudaEventDisableTiming);
        cudaEventCreateWithFlags(&ePrep, cudaEventDisableTiming);
        cudaEventCreateWithFlags(&eConv, cudaEventDisableTiming);
        cudaEventCreateWithFlags(&eProj, cudaEventDisableTiming);
        init_done = true;
    }

    const dim3 tblk(32, 32);
    const dim3 tgrid(2, 4, BB * HH);
    const dim3 ggrid(NPOS / 128);

    // ---- fork side stream ----
    cudaEventRecord(eFork, 0);
    cudaStreamWaitEvent(s1, eFork, 0);

    // s1: weight prep (rounded weights)
    prep_weights_kernel<<<CC, CC, 0, s1>>>(conv_w, in_proj_w, out_w, off_w, mask_w,
                                           off_b, mask_b, w0R, w1T, w3T, w2P, b2);
    cudaEventRecord(ePrep, s1);

    // s0: pack (rounds xt); conv waits for prep (overlapped with pack)
    pack_x_kernel<<<tgrid, tblk>>>(x, xt);
    cudaStreamWaitEvent(0, ePrep, 0);
    hmma_gemm_kernel<false, true><<<ggrid, 256, GEMM_SMEM>>>(xt, w0R, conv_b, y);
    cudaEventRecord(eConv, 0);

    // s1: in_proj (full fp32 out; parallel with dw branch)
    cudaStreamWaitEvent(s1, eConv, 0);
    hmma_gemm_kernel<false, false><<<ggrid, 256, GEMM_SMEM, s1>>>(y, w1T, in_proj_b, xproj);
    cudaEventRecord(eProj, s1);

    // s0: dw+LN+GELU (rounds dg) -> off_mask GEMM (full fp32 out)
    dw_ln_gelu_kernel<<<NPOS / 8, 256>>>(y, dw_w, dw_b, ln_g, ln_b, dg);
    hmma_gemm_kernel<false, false><<<ggrid, 256, GEMM_SMEM>>>(dg, w2P, b2, omp);

    // join: sampler needs xproj (s1) + omp (s0); rounds samp
    cudaStreamWaitEvent(0, eProj, 0);
    sampler_kernel<<<NPOS / 8, 256>>>(xproj, omp, samp);

    // out_proj writes NCHW directly (full fp32)
    hmma_gemm_kernel<true, false><<<ggrid, 256, GEMM_SMEM>>>(samp, w3T, out_b, out);
}

// round 16
// speedup vs baseline: 1.0686x; 1.0283x over previous
#include <cuda_runtime.h>
#include <math.h>
#include <cstdint>

// Problem constants
#define BB    8
#define CC    128
#define HIN   62
#define HH    64
#define WW    64
#define GG    4
#define GCC   32
#define PP    9
#define NPOS  (BB*HH*WW)   // 32768
#define HALF  (NPOS/2)     // 16384 (batches 0..3 / 4..7)

// Scratch (device globals; no allocation allowed)
__device__ float g_xt[NPOS*CC];      // tf32-rounded
__device__ float g_y[NPOS*CC];       // tf32-rounded
__device__ float g_xproj[NPOS*CC];   // full fp32 (sampler input)
__device__ float g_dg[NPOS*CC];      // tf32-rounded
__device__ float g_samp[NPOS*CC];    // tf32-rounded
__device__ float g_om[NPOS*CC];      // full fp32 (sampler input)
__device__ float g_w0R[CC*CC];       // conv_w rounded [n][k]
__device__ float g_w1T[CC*CC];       // in_proj_w transposed+rounded [n][k]
__device__ float g_w2P[CC*CC];       // off/mask fused, padded, rounded
__device__ float g_w3T[CC*CC];       // out_proj_w transposed+rounded
__device__ float g_b2[CC];

// ===========================================================================
__device__ __forceinline__ uint32_t f2tf32(float f) {
    uint32_t r;
    asm("cvt.rna.tf32.f32 %0, %1;" : "=r"(r) : "f"(f));
    return r;
}
__device__ __forceinline__ float tf32r(float f) { return __uint_as_float(f2tf32(f)); }
__device__ __forceinline__ void mma_tf32(float* c, const uint32_t* a, const uint32_t* b) {
    asm volatile(
        "mma.sync.aligned.m16n8k8.row.col.f32.tf32.tf32.f32 "
        "{%0,%1,%2,%3}, {%4,%5,%6,%7}, {%8,%9}, {%0,%1,%2,%3};"
        : "+f"(c[0]), "+f"(c[1]), "+f"(c[2]), "+f"(c[3])
        : "r"(a[0]), "r"(a[1]), "r"(a[2]), "r"(a[3]), "r"(b[0]), "r"(b[1]));
}
__device__ __forceinline__ uint32_t smem_u32(const void* p) {
    uint32_t a;
    asm("{ .reg .u64 t; cvta.to.shared.u64 t, %1; cvt.u32.u64 %0, t; }" : "=r"(a) : "l"(p));
    return a;
}
#define CP_ASYNC16(dst, src) \
    asm volatile("cp.async.cg.shared.global [%0], [%1], 16;" \
        :: "r"(dst), "l"(__cvta_generic_to_global(src)) : "memory")
#define CP_COMMIT() asm volatile("cp.async.commit_group;" ::: "memory")
#define CP_WAIT(n)  asm volatile("cp.async.wait_group %0;" :: "n"(n) : "memory")

// ===========================================================================
// Weight prep: transposes + fused/padded off-mask weight; ALL tf32-rounded.
// ===========================================================================
__global__ void prep_weights_kernel(const float* __restrict__ w0, const float* __restrict__ w1,
                                    const float* __restrict__ w3,
                                    const float* __restrict__ offw, const float* __restrict__ maskw,
                                    const float* __restrict__ offb, const float* __restrict__ maskb,
                                    float* __restrict__ w0R, float* __restrict__ w1T,
                                    float* __restrict__ w3T,
                                    float* __restrict__ w2P, float* __restrict__ b2) {
    const int n = blockIdx.x, k = threadIdx.x;
    w0R[n * CC + k] = tf32r(w0[n * CC + k]);     // conv_w already [co][ci]
    w1T[n * CC + k] = tf32r(w1[k * CC + n]);
    w3T[n * CC + k] = tf32r(w3[k * CC + n]);
    float v = 0.f;
    if (n < 72)       v = offw[k * 72 + n];
    else if (n < 108) v = maskw[k * 36 + (n - 72)];
    w2P[n * CC + k] = tf32r(v);
    if (k == 0) b2[n] = (n < 72) ? offb[n] : ((n < 108) ? maskb[n - 72] : 0.f);
}

// ===========================================================================
// x NCHW -> NHWC with 1-px zero border; tf32-rounded. z_off selects half.
// ===========================================================================
__global__ void pack_x_kernel(const float* __restrict__ x, float* __restrict__ xt,
                              int z_off) {
    __shared__ float t[32][33];
    const int bz = blockIdx.z + z_off;
    const int b  = bz >> 6;
    const int h  = bz & 63;
    const int w0 = blockIdx.x * 32;
    const int c0 = blockIdx.y * 32;
    const int tx = threadIdx.x, ty = threadIdx.y;
    const int hh = h - 1;
    const int ww = w0 + tx - 1;
    const int cc = c0 + ty;
    float v = 0.f;
    if (hh >= 0 && hh < HIN && ww >= 0 && ww < HIN)
        v = x[(((size_t)b * CC + cc) * HIN + hh) * HIN + ww];
    t[ty][tx] = v;
    __syncthreads();
    xt[(((size_t)b * HH + h) * WW + (w0 + ty)) * CC + (c0 + tx)] = tf32r(t[tx][ty]);
}

// ===========================================================================
// HMMA tf32 GEMM, FULL-N tile: M128 x N128, 4x K-chunk-32, 2-stage ring.
// m_off shifts the M range (half-batch pipelining).
// ===========================================================================
#define CH      32
#define CPITCH  36
#define STAGE_F (256 * CPITCH)
#define GEMM_SMEM (2 * STAGE_F * 4)       // 73728 bytes
#define SPITCH  132

template <bool TO_NCHW, bool ROUND_OUT>
__global__ void __launch_bounds__(256, 2)
hmma_gemm_kernel(const float* __restrict__ A, const float* __restrict__ Bm,
                 const float* __restrict__ bias, float* __restrict__ Cout,
                 int m_off) {
    extern __shared__ float smem[];
    const uint32_t sbase = smem_u32(smem);

    const int tid  = threadIdx.x;
    const int lane = tid & 31;
    const int wid  = tid >> 5;
    const int gid  = lane >> 2;
    const int tg   = lane & 3;
    const int warp_m = wid & 3;
    const int warp_n = wid >> 2;
    const int m0 = blockIdx.x * 128 + m_off;

    const int irow = tid >> 3;
    const int ic   = (tid & 7) * 4;
    auto issue = [&](int s, int kc) {
        const uint32_t st = sbase + (uint32_t)(s * STAGE_F * 4);
        #pragma unroll
        for (int i = 0; i < 4; i++) {
            const int row = irow + i * 32;
            CP_ASYNC16(st + (uint32_t)((row * CPITCH + ic) * 4),
                       A + (size_t)(m0 + row) * CC + kc + ic);
        }
        #pragma unroll
        for (int i = 0; i < 4; i++) {
            const int row = irow + i * 32;
            CP_ASYNC16(st + (uint32_t)(((128 + row) * CPITCH + ic) * 4),
                       Bm + (size_t)row * CC + kc + ic);
        }
        CP_COMMIT();
    };

    issue(0, 0);
    issue(1, CH);

    float acc[2][8][4];
    #pragma unroll
    for (int mi = 0; mi < 2; mi++)
        #pragma unroll
        for (int ni = 0; ni < 8; ni++)
            #pragma unroll
            for (int j = 0; j < 4; j++) acc[mi][ni][j] = 0.f;

    const int arow0 = warp_m * 32 + gid;
    const int bcol0 = warp_n * 64 + gid;

    auto mma_chunk = [&](int s) {
        const uint32_t* uA = reinterpret_cast<const uint32_t*>(smem + s * STAGE_F);
        const uint32_t* uB = uA + 128 * CPITCH;
        #pragma unroll
        for (int ks = 0; ks < 4; ks++) {
            const int k8 = ks * 8;
            uint32_t af[2][4];
            #pragma unroll
            for (int mi = 0; mi < 2; mi++) {
                const int r = arow0 + mi * 16;
                af[mi][0] = uA[(r    ) * CPITCH + k8 + tg];
                af[mi][1] = uA[(r + 8) * CPITCH + k8 + tg];
                af[mi][2] = uA[(r    ) * CPITCH + k8 + tg + 4];
                af[mi][3] = uA[(r + 8) * CPITCH + k8 + tg + 4];
            }
            #pragma unroll
            for (int ni = 0; ni < 8; ni++) {
                const int n = bcol0 + ni * 8;
                uint32_t bf[2];
                bf[0] = uB[n * CPITCH + k8 + tg];
                bf[1] = uB[n * CPITCH + k8 + tg + 4];
                mma_tf32(acc[0][ni], af[0], bf);
                mma_tf32(acc[1][ni], af[1], bf);
            }
        }
    };

    CP_WAIT(1);
    __syncthreads();
    mma_chunk(0);
    __syncthreads();
    issue(0, 2 * CH);
    CP_WAIT(1);
    __syncthreads();
    mma_chunk(1);
    __syncthreads();
    issue(1, 3 * CH);
    CP_WAIT(1);
    __syncthreads();
    mma_chunk(0);
    CP_WAIT(0);
    __syncthreads();
    mma_chunk(1);

    float2 bb[8];
    #pragma unroll
    for (int ni = 0; ni < 8; ni++) {
        const int col = warp_n * 64 + ni * 8 + 2 * tg;
        bb[ni].x = __ldg(bias + col);
        bb[ni].y = __ldg(bias + col + 1);
    }

    auto post = [&](float v) { return ROUND_OUT ? tf32r(v) : v; };

    if (!TO_NCHW) {
        #pragma unroll
        for (int mi = 0; mi < 2; mi++) {
            const int r0 = m0 + arow0 + mi * 16;
            #pragma unroll
            for (int ni = 0; ni < 8; ni++) {
                const int col = warp_n * 64 + ni * 8 + 2 * tg;
                float2 v0 = make_float2(post(acc[mi][ni][0] + bb[ni].x), post(acc[mi][ni][1] + bb[ni].y));
                float2 v1 = make_float2(post(acc[mi][ni][2] + bb[ni].x), post(acc[mi][ni][3] + bb[ni].y));
                *reinterpret_cast<float2*>(Cout + (size_t)r0 * CC + col)       = v0;
                *reinterpret_cast<float2*>(Cout + (size_t)(r0 + 8) * CC + col) = v1;
            }
        }
    } else {
        __syncthreads();
        float* sCT = smem;
        #pragma unroll
        for (int mi = 0; mi < 2; mi++) {
            #pragma unroll
            for (int ni = 0; ni < 8; ni++) {
                const int col = warp_n * 64 + ni * 8 + 2 * tg;
                const int r   = arow0 + mi * 16;
                sCT[(col    ) * SPITCH + r    ] = acc[mi][ni][0] + bb[ni].x;
                sCT[(col + 1) * SPITCH + r    ] = acc[mi][ni][1] + bb[ni].y;
                sCT[(col    ) * SPITCH + r + 8] = acc[mi][ni][2] + bb[ni].x;
                sCT[(col + 1) * SPITCH + r + 8] = acc[mi][ni][3] + bb[ni].y;
            }
        }
        __syncthreads();
        const int b       = m0 >> 12;
        const int inbatch = m0 & 4095;
        #pragma unroll
        for (int i = 0; i < 16; i++) {
            const int idx = i * 256 + tid;
            const int col = idx >> 5;
            const int rc  = idx & 31;
            const float4 v = *reinterpret_cast<const float4*>(sCT + col * SPITCH + rc * 4);
            *reinterpret_cast<float4*>(
                Cout + ((size_t)b * CC + col) * (HH * WW) + inbatch + rc * 4) = v;
        }
    }
}

// ===========================================================================
// Depthwise 3x3 (pad 1) + bias + LayerNorm(C) + exact GELU; tf32-rounded out.
// ===========================================================================
__global__ void __launch_bounds__(256)
dw_ln_gelu_kernel(const float* __restrict__ y,
                  const float* __restrict__ dww,
                  const float* __restrict__ dwb,
                  const float* __restrict__ lng,
                  const float* __restrict__ lnb,
                  float* __restrict__ out, int pos_off) {
    __shared__ float sW[9 * CC];
    const int tid = threadIdx.x;
    for (int i = tid; i < 9 * CC; i += 256) {
        const int c = i / 9, tap = i % 9;
        sW[tap * CC + c] = dww[i];
    }
    __syncthreads();

    const int wid  = tid >> 5;
    const int lane = tid & 31;
    const int pos  = blockIdx.x * 8 + wid + pos_off;
    const int b = pos >> 12;
    const int h = (pos >> 6) & 63;
    const int w = pos & 63;
    const int c4 = lane * 4;

    const float4 bv = __ldg(reinterpret_cast<const float4*>(dwb + c4));
    float4 acc = bv;
    const float* ybase = y + (((size_t)b * HH + h) * WW + w) * CC + c4;
    #pragma unroll
    for (int i = 0; i < 3; i++) {
        const int hh = h + i - 1;
        if ((unsigned)hh >= (unsigned)HH) continue;
        #pragma unroll
        for (int j = 0; j < 3; j++) {
            const int ww = w + j - 1;
            if ((unsigned)ww >= (unsigned)WW) continue;
            const float4 v = __ldg(reinterpret_cast<const float4*>(
                ybase + ((i - 1) * WW + (j - 1)) * CC));
            const float4 wt = *reinterpret_cast<const float4*>(sW + (i * 3 + j) * CC + c4);
            acc.x = fmaf(v.x, wt.x, acc.x);
            acc.y = fmaf(v.y, wt.y, acc.y);
            acc.z = fmaf(v.z, wt.z, acc.z);
            acc.w = fmaf(v.w, wt.w, acc.w);
        }
    }

    float s  = acc.x + acc.y + acc.z + acc.w;
    float s2 = acc.x * acc.x + acc.y * acc.y + acc.z * acc.z + acc.w * acc.w;
    #pragma unroll
    for (int o = 16; o > 0; o >>= 1) {
        s  += __shfl_xor_sync(0xFFFFFFFFu, s,  o);
        s2 += __shfl_xor_sync(0xFFFFFFFFu, s2, o);
    }
    const float mean = s * (1.f / CC);
    const float var  = s2 * (1.f / CC) - mean * mean;
    const float rstd = rsqrtf(var + 1e-5f);

    const float4 gv = __ldg(reinterpret_cast<const float4*>(lng + c4));
    const float4 betav = __ldg(reinterpret_cast<const float4*>(lnb + c4));
    float4 o4;
    {
        float v0 = (acc.x - mean) * rstd * gv.x + betav.x;
        float v1 = (acc.y - mean) * rstd * gv.y + betav.y;
        float v2 = (acc.z - mean) * rstd * gv.z + betav.z;
        float v3 = (acc.w - mean) * rstd * gv.w + betav.w;
        const float k = 0.70710678118654752440f;
        o4.x = tf32r(0.5f * v0 * (1.f + erff(v0 * k)));
        o4.y = tf32r(0.5f * v1 * (1.f + erff(v1 * k)));
        o4.z = tf32r(0.5f * v2 * (1.f + erff(v2 * k)));
        o4.w = tf32r(0.5f * v3 * (1.f + erff(v3 * k)));
    }
    *reinterpret_cast<float4*>(out + (size_t)pos * CC + c4) = o4;
}

// ===========================================================================
// DCNv3 bilinear sampler + fused group softmax; tf32-rounded out.
// ===========================================================================
__global__ void __launch_bounds__(256)
sampler_kernel(const float* __restrict__ xproj,
               const float* __restrict__ om,
               float* __restrict__ out, int pos_off) {
    __shared__ float sOM[8][112];
    const int tid  = threadIdx.x;
    const int wid  = tid >> 5;
    const int lane = tid & 31;
    const int pos  = blockIdx.x * 8 + wid + pos_off;
    const int b = pos >> 12;
    const int h = (pos >> 6) & 63;
    const int w = pos & 63;
    const int g  = lane >> 3;
    const int c4 = (lane & 7) * 4;

    #pragma unroll
    for (int r = 0; r < 4; r++) {
        const int i = r * 32 + lane;
        if (i < 108) sOM[wid][i] = __ldg(om + (size_t)pos * CC + i);
    }
    __syncwarp();

    const float* logit = &sOM[wid][72 + g * 9];
    float mx = -1e30f;
    #pragma unroll
    for (int p = 0; p < 9; p++) mx = fmaxf(mx, logit[p]);
    float se = 0.f;
    float ex[9];
    #pragma unroll
    for (int p = 0; p < 9; p++) { ex[p] = expf(logit[p] - mx); se += ex[p]; }
    const float inv_se = 1.f / se;

    const float* base = xproj + (size_t)b * (HH * WW * CC) + g * GCC + c4;
    float4 acc = make_float4(0.f, 0.f, 0.f, 0.f);
    #pragma unroll
    for (int p = 0; p < PP; p++) {
        const int gp = g * 9 + p;
        const float fix = (float)(w + p / 3) + sOM[wid][2 * gp];
        const float fiy = (float)(h + p % 3) + sOM[wid][2 * gp + 1];
        const float x0f = floorf(fix), y0f = floorf(fiy);
        const float fx = fix - x0f, fy = fiy - y0f;
        const int x0 = (int)x0f, y0 = (int)y0f;
        const float m = ex[p] * inv_se;

        const bool xv0 = (x0 >= 1) && (x0 <= 64);
        const bool xv1 = (x0 >= 0) && (x0 <= 63);
        const bool yv0 = (y0 >= 1) && (y0 <= 64);
        const bool yv1 = (y0 >= 0) && (y0 <= 63);
        float4 v00 = make_float4(0,0,0,0), v10 = v00, v01 = v00, v11 = v00;
        if (yv0 && xv0) v00 = __ldg(reinterpret_cast<const float4*>(base + ((size_t)(y0 - 1) * WW + (x0 - 1)) * CC));
        if (yv0 && xv1) v10 = __ldg(reinterpret_cast<const float4*>(base + ((size_t)(y0 - 1) * WW + (x0    )) * CC));
        if (yv1 && xv0) v01 = __ldg(reinterpret_cast<const float4*>(base + ((size_t)(y0    ) * WW + (x0 - 1)) * CC));
        if (yv1 && xv1) v11 = __ldg(reinterpret_cast<const float4*>(base + ((size_t)(y0    ) * WW + (x0    )) * CC));

        const float w00 = (1.f - fx) * (1.f - fy) * m;
        const float w10 = fx * (1.f - fy) * m;
        const float w01 = (1.f - fx) * fy * m;
        const float w11 = fx * fy * m;
        acc.x += v00.x * w00 + v10.x * w10 + v01.x * w01 + v11.x * w11;
        acc.y += v00.y * w00 + v10.y * w10 + v01.y * w01 + v11.y * w11;
        acc.z += v00.z * w00 + v10.z * w10 + v01.z * w01 + v11.z * w11;
        acc.w += v00.w * w00 + v10.w * w10 + v01.w * w01 + v11.w * w11;
    }
    float4 o4;
    o4.x = tf32r(acc.x); o4.y = tf32r(acc.y); o4.z = tf32r(acc.z); o4.w = tf32r(acc.w);
    *reinterpret_cast<float4*>(out + (size_t)pos * CC + g * GCC + c4) = o4;
}

// ===========================================================================
extern "C" void kernel_launch(void* const* d_in, const int* in_sizes, int n_in,
                              void* d_out, int out_size) {
    const float* x         = (const float*)d_in[0];
    const float* conv_w    = (const float*)d_in[1];
    const float* conv_b    = (const float*)d_in[2];
    const float* in_proj_w = (const float*)d_in[3];
    const float* in_proj_b = (const float*)d_in[4];
    const float* dw_w      = (const float*)d_in[5];
    const float* dw_b      = (const float*)d_in[6];
    const float* ln_g      = (const float*)d_in[7];
    const float* ln_b      = (const float*)d_in[8];
    const float* off_w     = (const float*)d_in[9];
    const float* off_b     = (const float*)d_in[10];
    const float* mask_w    = (const float*)d_in[11];
    const float* mask_b    = (const float*)d_in[12];
    const float* out_w     = (const float*)d_in[13];
    const float* out_b     = (const float*)d_in[14];
    float* out = (float*)d_out;

    float *xt, *y, *xproj, *dg, *samp, *omp, *w0R, *w1T, *w2P, *w3T, *b2;
    cudaGetSymbolAddress((void**)&xt,    g_xt);
    cudaGetSymbolAddress((void**)&y,     g_y);
    cudaGetSymbolAddress((void**)&xproj, g_xproj);
    cudaGetSymbolAddress((void**)&dg,    g_dg);
    cudaGetSymbolAddress((void**)&samp,  g_samp);
    cudaGetSymbolAddress((void**)&omp,   g_om);
    cudaGetSymbolAddress((void**)&w0R,   g_w0R);
    cudaGetSymbolAddress((void**)&w1T,   g_w1T);
    cudaGetSymbolAddress((void**)&w2P,   g_w2P);
    cudaGetSymbolAddress((void**)&w3T,   g_w3T);
    cudaGetSymbolAddress((void**)&b2,    g_b2);

    static cudaStream_t s1 = nullptr, s2 = nullptr;
    static cudaEvent_t eFork = nullptr, ePrep = nullptr;
    static cudaEvent_t eConv0 = nullptr, eConv1 = nullptr;
    static cudaEvent_t eP0 = nullptr, eP1 = nullptr, eS1 = nullptr;
    static bool init_done = false;
    if (!init_done) {
        cudaFuncSetAttribute((const void*)hmma_gemm_kernel<false, true>,
                             cudaFuncAttributeMaxDynamicSharedMemorySize, GEMM_SMEM);
        cudaFuncSetAttribute((const void*)hmma_gemm_kernel<false, false>,
                             cudaFuncAttributeMaxDynamicSharedMemorySize, GEMM_SMEM);
        cudaFuncSetAttribute((const void*)hmma_gemm_kernel<true, false>,
                             cudaFuncAttributeMaxDynamicSharedMemorySize, GEMM_SMEM);
        cudaStreamCreateWithFlags(&s1, cudaStreamNonBlocking);
        cudaStreamCreateWithFlags(&s2, cudaStreamNonBlocking);
        cudaEventCreateWithFlags(&eFork,  cudaEventDisableTiming);
        cudaEventCreateWithFlags(&ePrep,  cudaEventDisableTiming);
        cudaEventCreateWithFlags(&eConv0, cudaEventDisableTiming);
        cudaEventCreateWithFlags(&eConv1, cudaEventDisableTiming);
        cudaEventCreateWithFlags(&eP0,    cudaEventDisableTiming);
        cudaEventCreateWithFlags(&eP1,    cudaEventDisableTiming);
        cudaEventCreateWithFlags(&eS1,    cudaEventDisableTiming);
        init_done = true;
    }

    const dim3 tblk(32, 32);
    const dim3 tgrid(2, 4, BB * HH / 2);     // half: 256 z-slices
    const dim3 hgrid(HALF / 128);            // half GEMM: 128 CTAs
    const int  hsc = HALF / 8;               // half dw/sampler grid

    // ---- fork side streams ----
    cudaEventRecord(eFork, 0);
    cudaStreamWaitEvent(s1, eFork, 0);
    cudaStreamWaitEvent(s2, eFork, 0);

    // s1: weight prep
    prep_weights_kernel<<<CC, CC, 0, s1>>>(conv_w, in_proj_w, out_w, off_w, mask_w,
                                           off_b, mask_b, w0R, w1T, w3T, w2P, b2);
    cudaEventRecord(ePrep, s1);

    // s0: half0 pack + conv
    pack_x_kernel<<<tgrid, tblk>>>(x, xt, 0);
    cudaStreamWaitEvent(0, ePrep, 0);
    hmma_gemm_kernel<false, true><<<hgrid, 256, GEMM_SMEM>>>(xt, w0R, conv_b, y, 0);
    cudaEventRecord(eConv0, 0);

    // s2: in_proj half0
    cudaStreamWaitEvent(s2, eConv0, 0);
    hmma_gemm_kernel<false, false><<<hgrid, 256, GEMM_SMEM, s2>>>(y, w1T, in_proj_b, xproj, 0);
    cudaEventRecord(eP0, s2);

    // s1: half1 pack + conv (after prep, same stream)
    pack_x_kernel<<<tgrid, tblk, 0, s1>>>(x, xt, BB * HH / 2);
    hmma_gemm_kernel<false, true><<<hgrid, 256, GEMM_SMEM, s1>>>(xt, w0R, conv_b, y, HALF);
    cudaEventRecord(eConv1, s1);

    // s2: in_proj half1
    cudaStreamWaitEvent(s2, eConv1, 0);
    hmma_gemm_kernel<false, false><<<hgrid, 256, GEMM_SMEM, s2>>>(y, w1T, in_proj_b, xproj, HALF);
    cudaEventRecord(eP1, s2);

    // s0: half0 dw -> off -> samp -> out
    dw_ln_gelu_kernel<<<hsc, 256>>>(y, dw_w, dw_b, ln_g, ln_b, dg, 0);
    hmma_gemm_kernel<false, false><<<hgrid, 256, GEMM_SMEM>>>(dg, w2P, b2, omp, 0);
    cudaStreamWaitEvent(0, eP0, 0);
    sampler_kernel<<<hsc, 256>>>(xproj, omp, samp, 0);
    hmma_gemm_kernel<true, false><<<hgrid, 256, GEMM_SMEM>>>(samp, w3T, out_b, out, 0);

    // s1: half1 dw -> off -> samp -> out
    dw_ln_gelu_kernel<<<hsc, 256, 0, s1>>>(y, dw_w, dw_b, ln_g, ln_b, dg, HALF);
    hmma_gemm_kernel<false, false><<<hgrid, 256, GEMM_SMEM, s1>>>(dg, w2P, b2, omp, HALF);
    cudaStreamWaitEvent(s1, eP1, 0);
    sampler_kernel<<<hsc, 256, 0, s1>>>(xproj, omp, samp, HALF);
    hmma_gemm_kernel<true, false><<<hgrid, 256, GEMM_SMEM, s1>>>(samp, w3T, out_b, out, HALF);
    cudaEventRecord(eS1, s1);

    // join side streams back to origin
    cudaStreamWaitEvent(0, eS1, 0);
}